// round 13
// baseline (speedup 1.0000x reference)
#include <cuda_runtime.h>

// ---------------------------------------------------------------------------
// Compile-time G(3,0,1) blade algebra (verified: rel_err 8.5e-8).
// Basis order: 0:1 1:e0 2:e1 3:e2 4:e3 5:e01 6:e02 7:e03 8:e12 9:e13 10:e23
//              11:e012 12:e013 13:e023 14:e123 15:e0123
// ---------------------------------------------------------------------------

namespace ga {

__host__ __device__ constexpr int mask_of(int i) {
    const int t[16] = {0, 1, 2, 4, 8, 3, 5, 9, 6, 10, 12, 7, 11, 13, 14, 15};
    return t[i];
}
__host__ __device__ constexpr int idx_of(int m) {
    const int t[16] = {0, 1, 2, 5, 3, 6, 8, 11, 4, 7, 9, 12, 10, 13, 14, 15};
    return t[m];
}
__host__ __device__ constexpr int popc4(int m) {
    return (m & 1) + ((m >> 1) & 1) + ((m >> 2) & 1) + ((m >> 3) & 1);
}
__host__ __device__ constexpr int rsign(int a, int b) {
    int cnt = 0;
    for (int i = 1; i < 4; ++i)
        if ((a >> i) & 1) cnt += popc4(b & ((1 << i) - 1));
    return (cnt & 1) ? -1 : 1;
}

__host__ __device__ constexpr int gp_coef(int k, int j) {
    const int mk = mask_of(k), mj = mask_of(j);
    const int mi = mk ^ mj;
    if (mi & mj & 1) return 0;              // shared e0 -> metric 0
    return rsign(mi, mj);
}
__host__ __device__ constexpr int gp_src(int k, int j) {
    return idx_of(mask_of(k) ^ mask_of(j));
}

__host__ __device__ constexpr int jn_coef(int k, int j) {
    const int mk = mask_of(k), mj = mask_of(j);
    const int nmj = ~mj & 15;
    if (mk & nmj) return 0;                 // requires mk subset of mj
    const int mi = mk | nmj;
    return rsign(~mk & 15, mk)
         * rsign(mi, ~mi & 15)
         * rsign(mj, ~mj & 15)
         * rsign(~mi & 15, nmj);
}
__host__ __device__ constexpr int jn_src(int k, int j) {
    const int mk = mask_of(k), mj = mask_of(j);
    return idx_of(mk | (~mj & 15));
}

template <int K, int J>
__device__ __forceinline__ float gp_term(const float (&x)[16], const float (&y)[16]) {
    if constexpr (J >= 16) {
        return 0.0f;
    } else {
        float acc = gp_term<K, J + 1>(x, y);
        constexpr int c = gp_coef(K, J);
        constexpr int p = gp_src(K, J);
        if constexpr (c == 1)  acc = fmaf(x[p], y[J], acc);
        if constexpr (c == -1) acc = fmaf(-x[p], y[J], acc);
        return acc;
    }
}

template <int K, int J>
__device__ __forceinline__ float jn_term(const float (&x)[16], const float (&y)[16]) {
    if constexpr (J >= 16) {
        return 0.0f;
    } else {
        float acc = jn_term<K, J + 1>(x, y);
        constexpr int c = jn_coef(K, J);
        constexpr int p = jn_src(K, J);
        if constexpr (c == 1)  acc = fmaf(x[p], y[J], acc);
        if constexpr (c == -1) acc = fmaf(-x[p], y[J], acc);
        return acc;
    }
}

template <int K>
__device__ __forceinline__ float4 gp_quad(const float (&x)[16], const float (&y)[16]) {
    return make_float4(gp_term<K + 0, 0>(x, y), gp_term<K + 1, 0>(x, y),
                       gp_term<K + 2, 0>(x, y), gp_term<K + 3, 0>(x, y));
}

template <int K>
__device__ __forceinline__ float4 jn_quad(const float (&x)[16], const float (&y)[16],
                                          float r15) {
    return make_float4(r15 * jn_term<K + 0, 0>(x, y), r15 * jn_term<K + 1, 0>(x, y),
                       r15 * jn_term<K + 2, 0>(x, y), r15 * jn_term<K + 3, 0>(x, y));
}

}  // namespace ga

// ---------------------------------------------------------------------------
// R12 pipeline (proven best) repackaged into 64-thread CTAs. The kernel is
// entirely warp-private (__syncwarp only, per-warp smem), so block size is
// free to choose: 64 thr x 48 regs = 3072 regs/CTA -> 21 CTAs/SM = 42 warps
// (vs 40 at TPB=256), smem 21 x 9216B = 193KB (fits), and 8192 fine-grained
// CTAs erase the 2.77-wave tail quantization that held occupancy at 46%.
// ---------------------------------------------------------------------------

constexpr int TPB = 64;              // 2 warps per CTA
constexpr int WARPS_PER_CTA = TPB / 32;
constexpr int CH_STRIDE = 136;       // floats between staging chunk planes
constexpr int PITCH = 36;            // output row pitch: 144B, 16B-aligned
constexpr int WBUF = 32 * PITCH;     // 1152 floats (also >= 8*CH_STRIDE=1088)

__global__ __launch_bounds__(TPB, 21)
void MVGeometricBilinear_kernel(const float4* __restrict__ x4,
                                const float4* __restrict__ y4,
                                const float* __restrict__ ref,
                                float* __restrict__ out,
                                int npts) {
    __shared__ __align__(16) float smem[WARPS_PER_CTA][WBUF];   // 9216 B/CTA

    const int tid  = threadIdx.x;
    const int lane = tid & 31;
    const int w    = tid >> 5;
    const int P0   = blockIdx.x * TPB + w * 32;      // warp's first point
    const int p    = P0 + lane;

    float* wbuf = smem[w];

    // ---- 1. coalesced gmem -> smem (LDG.128 + STS.128 staging) ----
    {
        const int nv  = npts - P0;
        const int nv4 = nv <= 0 ? 0 : (nv >= 32 ? 128 : nv * 4);
        const float4* xw = x4 + (size_t)P0 * 4;
        const float4* yw = y4 + (size_t)P0 * 4;
#pragma unroll
        for (int i = 0; i < 4; ++i) {
            const int g = i * 32 + lane;             // float4 index in block
            if (g < nv4) {
                const int c  = g & 3;                // chunk within point
                const int pp = g >> 2;               // local point
                *(float4*)(wbuf + c * CH_STRIDE + pp * 4)       = __ldcs(xw + g);
                *(float4*)(wbuf + (4 + c) * CH_STRIDE + pp * 4) = __ldcs(yw + g);
            }
        }
    }
    const float r15 = (p < npts) ? __ldcs(ref + (size_t)p * 16 + 15) : 0.0f;
    __syncwarp();

    // ---- 2. smem -> regs (own point), conflict-free LDS.128 ----
    float x[16], y[16];
    if (p < npts) {
#pragma unroll
        for (int c = 0; c < 4; ++c) {
            const float4 vx = *(const float4*)(wbuf + c * CH_STRIDE + lane * 4);
            const float4 vy = *(const float4*)(wbuf + (4 + c) * CH_STRIDE + lane * 4);
            x[4*c+0]=vx.x; x[4*c+1]=vx.y; x[4*c+2]=vx.z; x[4*c+3]=vx.w;
            y[4*c+0]=vy.x; y[4*c+1]=vy.y; y[4*c+2]=vy.z; y[4*c+3]=vy.w;
        }
    }
    __syncwarp();   // all lanes done reading before buffer is overwritten

    // ---- 3. compute -> smem rows via STS.128 (pitch 36: conflict-free) ----
    if (p < npts) {
        float4* row4 = (float4*)(wbuf + lane * PITCH);
        row4[0] = ga::gp_quad<0>(x, y);
        row4[1] = ga::gp_quad<4>(x, y);
        row4[2] = ga::gp_quad<8>(x, y);
        row4[3] = ga::gp_quad<12>(x, y);
        row4[4] = ga::jn_quad<0>(x, y, r15);
        row4[5] = ga::jn_quad<4>(x, y, r15);
        row4[6] = ga::jn_quad<8>(x, y, r15);
        row4[7] = ga::jn_quad<12>(x, y, r15);
    }
    __syncwarp();

    // ---- 4. vectorized coalesced writeback: 8x (LDS.128 + STG.128) ----
    // instr i, lane L covers warp-block floats 128i+4L..+3
    //   = row (4i + L/8), comps 4(L%8)..+3; smem banks 4(L%8): conflict-free.
    const int nvalid = npts - P0;
    float* outw = out + (size_t)P0 * 32;
    if (nvalid >= 32) {
#pragma unroll
        for (int i = 0; i < 8; ++i) {
            const int r = 4 * i + (lane >> 3);
            const int c = 4 * (lane & 7);
            const float4 v = *(const float4*)(wbuf + r * PITCH + c);
            __stcs((float4*)(outw + 128 * i + 4 * lane), v);
        }
    } else if (nvalid > 0) {
        for (int i = 0; i < nvalid; ++i)
            __stcs(outw + 32 * i + lane, wbuf[i * PITCH + lane]);
    }
}

extern "C" void kernel_launch(void* const* d_in, const int* in_sizes, int n_in,
                              void* d_out, int out_size) {
    const float* x   = (const float*)d_in[0];
    const float* y   = (const float*)d_in[1];
    const float* ref = (const float*)d_in[2];
    float* out       = (float*)d_out;

    const int npts = in_sizes[0] / 16;
    const int blocks = (npts + TPB - 1) / TPB;

    MVGeometricBilinear_kernel<<<blocks, TPB>>>(
        (const float4*)x, (const float4*)y, ref, out, npts);
}

// round 14
// speedup vs baseline: 1.4242x; 1.4242x over previous
#include <cuda_runtime.h>

// ---------------------------------------------------------------------------
// Compile-time G(3,0,1) blade algebra (verified: rel_err 8.5e-8).
// Basis order: 0:1 1:e0 2:e1 3:e2 4:e3 5:e01 6:e02 7:e03 8:e12 9:e13 10:e23
//              11:e012 12:e013 13:e023 14:e123 15:e0123
// ---------------------------------------------------------------------------

namespace ga {

__host__ __device__ constexpr int mask_of(int i) {
    const int t[16] = {0, 1, 2, 4, 8, 3, 5, 9, 6, 10, 12, 7, 11, 13, 14, 15};
    return t[i];
}
__host__ __device__ constexpr int idx_of(int m) {
    const int t[16] = {0, 1, 2, 5, 3, 6, 8, 11, 4, 7, 9, 12, 10, 13, 14, 15};
    return t[m];
}
__host__ __device__ constexpr int popc4(int m) {
    return (m & 1) + ((m >> 1) & 1) + ((m >> 2) & 1) + ((m >> 3) & 1);
}
__host__ __device__ constexpr int rsign(int a, int b) {
    int cnt = 0;
    for (int i = 1; i < 4; ++i)
        if ((a >> i) & 1) cnt += popc4(b & ((1 << i) - 1));
    return (cnt & 1) ? -1 : 1;
}

__host__ __device__ constexpr int gp_coef(int k, int j) {
    const int mk = mask_of(k), mj = mask_of(j);
    const int mi = mk ^ mj;
    if (mi & mj & 1) return 0;              // shared e0 -> metric 0
    return rsign(mi, mj);
}
__host__ __device__ constexpr int gp_src(int k, int j) {
    return idx_of(mask_of(k) ^ mask_of(j));
}

__host__ __device__ constexpr int jn_coef(int k, int j) {
    const int mk = mask_of(k), mj = mask_of(j);
    const int nmj = ~mj & 15;
    if (mk & nmj) return 0;                 // requires mk subset of mj
    const int mi = mk | nmj;
    return rsign(~mk & 15, mk)
         * rsign(mi, ~mi & 15)
         * rsign(mj, ~mj & 15)
         * rsign(~mi & 15, nmj);
}
__host__ __device__ constexpr int jn_src(int k, int j) {
    const int mk = mask_of(k), mj = mask_of(j);
    return idx_of(mk | (~mj & 15));
}

template <int K, int J>
__device__ __forceinline__ float gp_term(const float (&x)[16], const float (&y)[16]) {
    if constexpr (J >= 16) {
        return 0.0f;
    } else {
        float acc = gp_term<K, J + 1>(x, y);
        constexpr int c = gp_coef(K, J);
        constexpr int p = gp_src(K, J);
        if constexpr (c == 1)  acc = fmaf(x[p], y[J], acc);
        if constexpr (c == -1) acc = fmaf(-x[p], y[J], acc);
        return acc;
    }
}

template <int K, int J>
__device__ __forceinline__ float jn_term(const float (&x)[16], const float (&y)[16]) {
    if constexpr (J >= 16) {
        return 0.0f;
    } else {
        float acc = jn_term<K, J + 1>(x, y);
        constexpr int c = jn_coef(K, J);
        constexpr int p = jn_src(K, J);
        if constexpr (c == 1)  acc = fmaf(x[p], y[J], acc);
        if constexpr (c == -1) acc = fmaf(-x[p], y[J], acc);
        return acc;
    }
}

template <int K>
__device__ __forceinline__ float4 gp_quad(const float (&x)[16], const float (&y)[16]) {
    return make_float4(gp_term<K + 0, 0>(x, y), gp_term<K + 1, 0>(x, y),
                       gp_term<K + 2, 0>(x, y), gp_term<K + 3, 0>(x, y));
}

template <int K>
__device__ __forceinline__ float4 jn_quad(const float (&x)[16], const float (&y)[16],
                                          float r15) {
    return make_float4(r15 * jn_term<K + 0, 0>(x, y), r15 * jn_term<K + 1, 0>(x, y),
                       r15 * jn_term<K + 2, 0>(x, y), r15 * jn_term<K + 3, 0>(x, y));
}

}  // namespace ga

// ---------------------------------------------------------------------------
// R12 pipeline at TPB=128, 10 CTAs/SM. Same 40-warp/SM and 48-reg budget as
// R12 (10 warps/SMSP x 48 x 32 = 15360 <= 16384 regfile: fits, unlike R13's
// 21x2 config which forced a 40-reg squeeze), but halved CTA granularity
// shrinks wave-tail quantization and slowest-warp-holds-CTA waste.
// ---------------------------------------------------------------------------

constexpr int TPB = 128;             // 4 warps per CTA
constexpr int WARPS_PER_CTA = TPB / 32;
constexpr int CH_STRIDE = 136;       // floats between staging chunk planes
constexpr int PITCH = 36;            // output row pitch: 144B, 16B-aligned
constexpr int WBUF = 32 * PITCH;     // 1152 floats (also >= 8*CH_STRIDE=1088)

__global__ __launch_bounds__(TPB, 10)
void MVGeometricBilinear_kernel(const float4* __restrict__ x4,
                                const float4* __restrict__ y4,
                                const float* __restrict__ ref,
                                float* __restrict__ out,
                                int npts) {
    __shared__ __align__(16) float smem[WARPS_PER_CTA][WBUF];   // 18432 B/CTA

    const int tid  = threadIdx.x;
    const int lane = tid & 31;
    const int w    = tid >> 5;
    const int P0   = blockIdx.x * TPB + w * 32;      // warp's first point
    const int p    = P0 + lane;

    float* wbuf = smem[w];

    // ---- 1. coalesced gmem -> smem (LDG.128 + STS.128 staging) ----
    {
        const int nv  = npts - P0;
        const int nv4 = nv <= 0 ? 0 : (nv >= 32 ? 128 : nv * 4);
        const float4* xw = x4 + (size_t)P0 * 4;
        const float4* yw = y4 + (size_t)P0 * 4;
#pragma unroll
        for (int i = 0; i < 4; ++i) {
            const int g = i * 32 + lane;             // float4 index in block
            if (g < nv4) {
                const int c  = g & 3;                // chunk within point
                const int pp = g >> 2;               // local point
                *(float4*)(wbuf + c * CH_STRIDE + pp * 4)       = __ldcs(xw + g);
                *(float4*)(wbuf + (4 + c) * CH_STRIDE + pp * 4) = __ldcs(yw + g);
            }
        }
    }
    const float r15 = (p < npts) ? __ldcs(ref + (size_t)p * 16 + 15) : 0.0f;
    __syncwarp();

    // ---- 2. smem -> regs (own point), conflict-free LDS.128 ----
    float x[16], y[16];
    if (p < npts) {
#pragma unroll
        for (int c = 0; c < 4; ++c) {
            const float4 vx = *(const float4*)(wbuf + c * CH_STRIDE + lane * 4);
            const float4 vy = *(const float4*)(wbuf + (4 + c) * CH_STRIDE + lane * 4);
            x[4*c+0]=vx.x; x[4*c+1]=vx.y; x[4*c+2]=vx.z; x[4*c+3]=vx.w;
            y[4*c+0]=vy.x; y[4*c+1]=vy.y; y[4*c+2]=vy.z; y[4*c+3]=vy.w;
        }
    }
    __syncwarp();   // all lanes done reading before buffer is overwritten

    // ---- 3. compute -> smem rows via STS.128 (pitch 36: conflict-free) ----
    if (p < npts) {
        float4* row4 = (float4*)(wbuf + lane * PITCH);
        row4[0] = ga::gp_quad<0>(x, y);
        row4[1] = ga::gp_quad<4>(x, y);
        row4[2] = ga::gp_quad<8>(x, y);
        row4[3] = ga::gp_quad<12>(x, y);
        row4[4] = ga::jn_quad<0>(x, y, r15);
        row4[5] = ga::jn_quad<4>(x, y, r15);
        row4[6] = ga::jn_quad<8>(x, y, r15);
        row4[7] = ga::jn_quad<12>(x, y, r15);
    }
    __syncwarp();

    // ---- 4. vectorized coalesced writeback: 8x (LDS.128 + STG.128) ----
    // instr i, lane L covers warp-block floats 128i+4L..+3
    //   = row (4i + L/8), comps 4(L%8)..+3; smem banks 4(L%8): conflict-free.
    const int nvalid = npts - P0;
    float* outw = out + (size_t)P0 * 32;
    if (nvalid >= 32) {
#pragma unroll
        for (int i = 0; i < 8; ++i) {
            const int r = 4 * i + (lane >> 3);
            const int c = 4 * (lane & 7);
            const float4 v = *(const float4*)(wbuf + r * PITCH + c);
            __stcs((float4*)(outw + 128 * i + 4 * lane), v);
        }
    } else if (nvalid > 0) {
        for (int i = 0; i < nvalid; ++i)
            __stcs(outw + 32 * i + lane, wbuf[i * PITCH + lane]);
    }
}

extern "C" void kernel_launch(void* const* d_in, const int* in_sizes, int n_in,
                              void* d_out, int out_size) {
    const float* x   = (const float*)d_in[0];
    const float* y   = (const float*)d_in[1];
    const float* ref = (const float*)d_in[2];
    float* out       = (float*)d_out;

    const int npts = in_sizes[0] / 16;
    const int blocks = (npts + TPB - 1) / TPB;

    MVGeometricBilinear_kernel<<<blocks, TPB>>>(
        (const float4*)x, (const float4*)y, ref, out, npts);
}